// round 14
// baseline (speedup 1.0000x reference)
#include <cuda_runtime.h>
#include <cuda_fp16.h>
#include <math.h>

#define BB 8
#define CIN 128
#define COUT 128
#define KN 4
#define HH 160
#define WW 160
#define ATT 16
#define MID 32
#define HW (HH*WW)
#define IKK (CIN*9)
#define PB 16

#define NPX 128
#define NTHR 256
#define STG_BYTES 32768        // per stage: A 16KB + B 16KB (fp16, K-chunk 64)
#define SMEM_BYTES (2*STG_BYTES)
#define NTILE 200              // spatial tiles for stats partials

__device__ float g_gap0[BB*CIN];
__device__ float g_gap1[BB*CIN];
__device__ float g_fdmean[BB*CIN];
__device__ float g_fdmax[BB*CIN];
__device__ float g_ps0[BB*CIN*NTILE];
__device__ float g_ps1[BB*CIN*NTILE];
__device__ float g_pmx[BB*CIN*NTILE];
__device__ float g_ca[PB*CIN];
__device__ float g_fa[PB*COUT];
__device__ float g_sM[PB*9];
__device__ float g_ka[PB*KN];
__device__ float g_A[PB*COUT*IKK];
__device__ float g_fuseT[2*COUT*COUT];
__device__ __align__(16) __half g_WfT[(size_t)PB*9*COUT*CIN];  // [pb][tap][oc][ic]
__device__ __align__(16) __half g_xT[(size_t)PB*HW*CIN];       // fp16 NHWC

__device__ __forceinline__ float sigm(float x){ return 1.f/(1.f+expf(-x)); }
__device__ __forceinline__ unsigned smem_u32(const void* p){
    unsigned a;
    asm("{ .reg .u64 t; cvta.to.shared.u64 t, %1; cvt.u32.u64 %0, t; }" : "=r"(a) : "l"(p));
    return a;
}
__device__ __forceinline__ void mma_f16(float* c, const unsigned* a, const unsigned* b){
    asm volatile(
        "mma.sync.aligned.m16n8k16.row.col.f32.f16.f16.f32 "
        "{%0,%1,%2,%3}, {%4,%5,%6,%7}, {%8,%9}, {%0,%1,%2,%3};"
        : "+f"(c[0]), "+f"(c[1]), "+f"(c[2]), "+f"(c[3])
        : "r"(a[0]), "r"(a[1]), "r"(a[2]), "r"(a[3]), "r"(b[0]), "r"(b[1]));
}
__device__ __forceinline__ void ldsm4(unsigned* d, unsigned addr){
    asm volatile("ldmatrix.sync.aligned.m8n8.x4.shared.b16 {%0,%1,%2,%3}, [%4];"
        : "=r"(d[0]),"=r"(d[1]),"=r"(d[2]),"=r"(d[3]) : "r"(addr));
}
__device__ __forceinline__ void cp16(unsigned dst, const void* src, unsigned sz){
    asm volatile("cp.async.ca.shared.global [%0], [%1], 16, %2;"
        :: "r"(dst), "l"(src), "r"(sz) : "memory");
}

// ---------------- k_trs : NCHW fp32 -> NHWC fp16 (both paths) + stats partials
__global__ __launch_bounds__(256) void k_trs(const float* __restrict__ x0,
                                             const float* __restrict__ x1){
    int px0 = blockIdx.x*128, ic0 = blockIdx.y*32, b = blockIdx.z;
    const float* s0 = x0 + ((size_t)b*CIN + ic0)*HW + px0;
    const float* s1 = x1 + ((size_t)b*CIN + ic0)*HW + px0;
    __shared__ float t0[32][129], t1[32][129];
    int tid = threadIdx.x, lane = tid & 31, w = tid >> 5;
    #pragma unroll
    for (int i=0;i<4;++i){
        int ic = w + i*8;
        float4 v = *(const float4*)(s0 + (size_t)ic*HW + lane*4);
        t0[ic][lane*4+0]=v.x; t0[ic][lane*4+1]=v.y; t0[ic][lane*4+2]=v.z; t0[ic][lane*4+3]=v.w;
        float4 u = *(const float4*)(s1 + (size_t)ic*HW + lane*4);
        t1[ic][lane*4+0]=u.x; t1[ic][lane*4+1]=u.y; t1[ic][lane*4+2]=u.z; t1[ic][lane*4+3]=u.w;
    }
    __syncthreads();
    {
        int px = tid >> 1, icg = (tid & 1)*16;
        __half* d0 = g_xT + ((size_t)b*HW + px0 + px)*CIN + ic0 + icg;
        __half* d1 = g_xT + ((size_t)(b+8)*HW + px0 + px)*CIN + ic0 + icg;
        unsigned v[8], u[8];
        #pragma unroll
        for (int j=0;j<8;++j){
            __half2 h0 = __floats2half2_rn(t0[icg+2*j][px], t0[icg+2*j+1][px]);
            __half2 h1 = __floats2half2_rn(t1[icg+2*j][px], t1[icg+2*j+1][px]);
            v[j] = *(unsigned*)&h0; u[j] = *(unsigned*)&h1;
        }
        *(uint4*)(d0)     = make_uint4(v[0],v[1],v[2],v[3]);
        *(uint4*)(d0 + 8) = make_uint4(v[4],v[5],v[6],v[7]);
        *(uint4*)(d1)     = make_uint4(u[0],u[1],u[2],u[3]);
        *(uint4*)(d1 + 8) = make_uint4(u[4],u[5],u[6],u[7]);
    }
    // stats partials: per ic, 8 lanes x 16 px each
    int ic = tid >> 3, seg = tid & 7;
    float a0=0.f, a1=0.f, mx=-3.0e38f;
    #pragma unroll
    for (int j=0;j<16;++j){
        float v0 = t0[ic][seg*16+j], v1 = t1[ic][seg*16+j];
        a0 += v0; a1 += v1; mx = fmaxf(mx, v0-v1);
    }
    #pragma unroll
    for (int off=4; off; off>>=1){
        a0 += __shfl_down_sync(0xffffffffu, a0, off, 8);
        a1 += __shfl_down_sync(0xffffffffu, a1, off, 8);
        mx  = fmaxf(mx, __shfl_down_sync(0xffffffffu, mx, off, 8));
    }
    if (seg == 0){
        int bc = b*CIN + ic0 + ic;
        g_ps0[bc*NTILE + blockIdx.x] = a0;
        g_ps1[bc*NTILE + blockIdx.x] = a1;
        g_pmx[bc*NTILE + blockIdx.x] = mx;
    }
}

// ---------------- k_red : fold 200 partials per (b,c) ----------------
__global__ __launch_bounds__(64) void k_red(){
    int bc = blockIdx.x, tid = threadIdx.x;
    float s0=0.f, s1=0.f, mx=-3.0e38f;
    for (int i=tid;i<NTILE;i+=64){
        s0 += g_ps0[bc*NTILE+i];
        s1 += g_ps1[bc*NTILE+i];
        mx  = fmaxf(mx, g_pmx[bc*NTILE+i]);
    }
    __shared__ float r0[2], r1[2], rm[2];
    #pragma unroll
    for (int off=16; off; off>>=1){
        s0 += __shfl_down_sync(0xffffffffu, s0, off);
        s1 += __shfl_down_sync(0xffffffffu, s1, off);
        mx  = fmaxf(mx, __shfl_down_sync(0xffffffffu, mx, off));
    }
    if ((tid & 31) == 0){ r0[tid>>5]=s0; r1[tid>>5]=s1; rm[tid>>5]=mx; }
    __syncthreads();
    if (tid == 0){
        float S0=r0[0]+r0[1], S1=r1[0]+r1[1], M=fmaxf(rm[0],rm[1]);
        const float inv = 1.f/(float)HW;
        g_gap0[bc]=S0*inv; g_gap1[bc]=S1*inv; g_fdmean[bc]=(S0-S1)*inv; g_fdmax[bc]=M;
    }
}

// ---------------- k_att ----------------
__global__ __launch_bounds__(128) void k_att(
    const float* __restrict__ fc_w,  const float* __restrict__ ln_g,  const float* __restrict__ ln_b,
    const float* __restrict__ ch_w,  const float* __restrict__ ch_b,
    const float* __restrict__ fl_w,  const float* __restrict__ fl_b,
    const float* __restrict__ sp_w,  const float* __restrict__ sp_b,
    const float* __restrict__ kn_w,  const float* __restrict__ kn_b,
    const float* __restrict__ mlp_w1,const float* __restrict__ mlp_b1,
    const float* __restrict__ mlp_w2,const float* __restrict__ mlp_b2)
{
    int b = blockIdx.x, tid = threadIdx.x;
    __shared__ float gA[128], gB[128], yv[ATT], hs[MID], mfd[9], kl[KN];
    gA[tid] = g_fdmean[b*CIN + tid];
    gB[tid] = g_fdmax [b*CIN + tid];
    __syncthreads();
    if (tid < MID){
        float sa_ = mlp_b1[tid], sm_ = mlp_b1[tid];
        for (int c=0;c<CIN;++c){ float w = mlp_w1[tid*CIN+c]; sa_ += w*gA[c]; sm_ += w*gB[c]; }
        hs[tid] = fmaxf(sa_,0.f) + fmaxf(sm_,0.f);
    }
    __syncthreads();
    if (tid < 9){
        float z = 2.f*mlp_b2[tid];
        for (int t=0;t<MID;++t) z += mlp_w2[tid*MID+t]*hs[t];
        mfd[tid] = sigm(z);
    }
    for (int p=0;p<2;++p){
        __syncthreads();
        gA[tid] = (p ? g_gap1 : g_gap0)[b*CIN + tid];
        __syncthreads();
        if (tid < ATT){
            float v = 0.f;
            for (int c=0;c<CIN;++c) v += fc_w[tid*CIN+c]*gA[c];
            yv[tid] = v;
        }
        __syncthreads();
        if (tid == 0){
            float mu = 0.f;
            for (int j=0;j<ATT;++j) mu += yv[j];
            mu *= (1.f/ATT);
            float var = 0.f;
            for (int j=0;j<ATT;++j){ float d = yv[j]-mu; var += d*d; }
            var *= (1.f/ATT);
            float inv = rsqrtf(var + 1e-5f);
            for (int j=0;j<ATT;++j)
                yv[j] = fmaxf(0.f, (yv[j]-mu)*inv*ln_g[j] + ln_b[j]);
        }
        __syncthreads();
        {
            float ac = ch_b[tid], af = fl_b[tid];
            for (int j=0;j<ATT;++j){ ac += ch_w[tid*ATT+j]*yv[j]; af += fl_w[tid*ATT+j]*yv[j]; }
            g_ca[(p*BB+b)*CIN  + tid] = sigm(ac);
            g_fa[(p*BB+b)*COUT + tid] = sigm(af);
        }
        if (tid < 9){
            float s = sp_b[tid];
            for (int j=0;j<ATT;++j) s += sp_w[tid*ATT+j]*yv[j];
            g_sM[(p*BB+b)*9 + tid] = sigm(s)*mfd[tid];
        }
        if (tid < KN){
            float l = kn_b[tid];
            for (int j=0;j<ATT;++j) l += kn_w[tid*ATT+j]*yv[j];
            kl[tid] = l;
        }
        __syncthreads();
        if (tid == 0){
            float m = fmaxf(fmaxf(kl[0],kl[1]), fmaxf(kl[2],kl[3]));
            float e0=expf(kl[0]-m), e1=expf(kl[1]-m), e2=expf(kl[2]-m), e3=expf(kl[3]-m);
            float s = e0+e1+e2+e3;
            g_ka[(p*BB+b)*KN+0]=e0/s; g_ka[(p*BB+b)*KN+1]=e1/s;
            g_ka[(p*BB+b)*KN+2]=e2/s; g_ka[(p*BB+b)*KN+3]=e3/s;
        }
    }
}

// ---------------- k_agg ----------------
__global__ __launch_bounds__(256) void k_agg(const float* __restrict__ weight){
    int pb  = blockIdx.y;
    int idx = blockIdx.x*256 + threadIdx.x;
    int c   = idx / IKK;
    float k0=g_ka[pb*KN+0], k1=g_ka[pb*KN+1], k2=g_ka[pb*KN+2], k3=g_ka[pb*KN+3];
    const float* w = weight + idx;
    float acc = k0*w[0] + k1*w[COUT*IKK] + k2*w[2*COUT*IKK] + k3*w[3*COUT*IKK];
    g_A[pb*(COUT*IKK) + idx] = acc * g_fa[pb*COUT + c];
}

// ---------------- k_ftr ----------------
__global__ __launch_bounds__(128) void k_ftr(const float* __restrict__ fuse_w){
    int c = blockIdx.x, o = threadIdx.x;
    g_fuseT[c*COUT + o] = fuse_w[o*(2*COUT) + c];
}

// ---------------- k_wf : fuse-GEMM + scales -> fp16 [tap][oc][ic] ----------
// grid (36 ntiles of 32 ikk, 16 pb) — 576 blocks for >1 wave occupancy.
__global__ __launch_bounds__(256) void k_wf(){
    int pb = blockIdx.y, p = pb >> 3;
    int nt = blockIdx.x;
    int tid = threadIdx.x;
    int to = tid & 15, tn = tid >> 4;
    __shared__ __align__(16) float Fs[16][128];
    __shared__ __align__(16) float As[16][32];
    float acc[8][2];
    #pragma unroll
    for (int o=0;o<8;++o){ acc[o][0]=0.f; acc[o][1]=0.f; }
    const float* Abase = g_A + (size_t)pb*(COUT*IKK);
    for (int ck=0; ck<8; ++ck){
        __syncthreads();
        #pragma unroll
        for (int j=0;j<8;++j){
            int l = j*256 + tid; int o = l & 127, cc = l >> 7;
            Fs[cc][o] = g_fuseT[(p*COUT + ck*16 + cc)*COUT + o];
        }
        {
            int l = tid*2; int nn = l & 31, cc = l >> 5;
            *(float2*)&As[cc][nn] = *(const float2*)&Abase[(ck*16+cc)*IKK + nt*32 + nn];
        }
        __syncthreads();
        #pragma unroll
        for (int cc=0; cc<16; ++cc){
            float2 av = *(const float2*)&As[cc][tn*2];
            float4 f0 = *(const float4*)&Fs[cc][to*8];
            float4 f1 = *(const float4*)&Fs[cc][to*8+4];
            float f_[8] = {f0.x,f0.y,f0.z,f0.w, f1.x,f1.y,f1.z,f1.w};
            #pragma unroll
            for (int o=0;o<8;++o){
                acc[o][0] = fmaf(f_[o], av.x, acc[o][0]);
                acc[o][1] = fmaf(f_[o], av.y, acc[o][1]);
            }
        }
    }
    __half* Wbase = g_WfT + (size_t)pb*9*COUT*CIN;
    const float* cap = g_ca + pb*CIN;
    const float* sMp = g_sM + pb*9;
    #pragma unroll
    for (int n=0;n<2;++n){
        int ikk = nt*32 + tn*2 + n;
        int ic = ikk/9, tap = ikk - ic*9;
        float sc = cap[ic]*sMp[tap];
        #pragma unroll
        for (int o=0;o<8;++o){
            int oc = to*8 + o;
            Wbase[((size_t)tap*COUT + oc)*CIN + ic] = __float2half_rn(acc[o][n]*sc);
        }
    }
}

// ---------------- k_conv : fp16 mma.sync m16n8k16, K-chunk 64, 2-stage ------
__global__ __launch_bounds__(NTHR, 2) void k_conv(const float* __restrict__ fuse_b,
                                                  float* __restrict__ out){
    extern __shared__ float dsm[];
    __shared__ float sBias[128];
    int b = blockIdx.y;
    int px0 = blockIdx.x*NPX;
    int tid = threadIdx.x;
    int lane = tid & 31, wid = tid >> 5;
    int wm = wid >> 2, wn = wid & 3;
    int g = lane >> 2, tg = lane & 3;
    int sel = lane >> 3, r8 = lane & 7;
    int rowA = r8 + ((sel & 1) << 3), kselA = sel >> 1;
    int rowB = r8 + ((sel >> 1) << 3), kselB = sel & 1;
    if (tid < 128) sBias[tid] = fuse_b[tid];
    unsigned smem_base = smem_u32(dsm);

    unsigned aoff[4], boff[2];
    #pragma unroll
    for (int mt=0;mt<4;++mt) aoff[mt] = (wm*64 + mt*16 + rowA)*128;
    #pragma unroll
    for (int q=0;q<2;++q)    boff[q] = 16384 + (wn*32 + q*16 + rowB)*128;

    unsigned dstA[4]; int srcA[4];
    #pragma unroll
    for (int j=0;j<4;++j){
        int idx = j*NTHR + tid;
        int oc = idx>>3, c8 = idx&7;
        dstA[j] = oc*128 + ((c8 ^ (oc&7))<<4);
        srcA[j] = oc*CIN + c8*8;
    }
    unsigned dstB[4]; int srcB[4]; unsigned bmask[4];
    #pragma unroll
    for (int j=0;j<4;++j){
        int idx = j*NTHR + tid;
        int px = idx>>3, c8 = idx&7;
        dstB[j] = 16384 + px*128 + ((c8 ^ (px&7))<<4);
        int pg = px0 + px;
        int y = pg/WW, x = pg - y*WW;
        srcB[j] = (y*WW + x - WW - 1)*CIN + c8*8;
        unsigned m = 0;
        #pragma unroll
        for (int tap=0;tap<9;++tap){
            int dy = tap/3, dx = tap - dy*3;
            bool ok = ((unsigned)(y+dy-1) < (unsigned)HH) && ((unsigned)(x+dx-1) < (unsigned)WW);
            m |= (ok ? 1u : 0u) << tap;
        }
        bmask[j] = m;
    }

    float acc[4][4][4];
    #pragma unroll
    for (int mt=0;mt<4;++mt)
        #pragma unroll
        for (int nt=0;nt<4;++nt)
            #pragma unroll
            for (int e=0;e<4;++e) acc[mt][nt][e]=0.f;

    auto stage_issue = [&](int c, int slot){
        int p = (c>=18) ? 1 : 0;
        int rr = c - p*18;
        int tap = rr>>1, ich = rr&1;
        int dy = tap/3, dx = tap - dy*3;
        int pb = p*BB + b;
        unsigned sbase = smem_base + slot*STG_BYTES;
        const __half* Ab = g_WfT + ((size_t)pb*9 + tap)*COUT*CIN + ich*64;
        #pragma unroll
        for (int j=0;j<4;++j)
            cp16(sbase + dstA[j], Ab + srcA[j], 16);
        const __half* Bb = g_xT + (size_t)pb*HW*CIN + (dy*WW + dx)*CIN + ich*64;
        unsigned tb = 1u << tap;
        #pragma unroll
        for (int j=0;j<4;++j)
            cp16(sbase + dstB[j], Bb + srcB[j], (bmask[j] & tb) ? 16u : 0u);
        asm volatile("cp.async.commit_group;" ::: "memory");
    };

    stage_issue(0, 0);
    stage_issue(1, 1);
    for (int c=0;c<36;++c){
        if (c < 34) asm volatile("cp.async.wait_group 1;" ::: "memory");
        else        asm volatile("cp.async.wait_group 0;" ::: "memory");
        __syncthreads();
        unsigned base = smem_base + (c&1)*STG_BYTES;
        #pragma unroll
        for (int ks=0;ks<4;++ks){
            unsigned kA = (unsigned)(((ks*2 + kselA) ^ r8) << 4);
            unsigned kB = (unsigned)(((ks*2 + kselB) ^ r8) << 4);
            unsigned af[4][4], bf[2][4];
            #pragma unroll
            for (int mt=0;mt<4;++mt) ldsm4(af[mt], base + aoff[mt] + kA);
            #pragma unroll
            for (int q=0;q<2;++q)    ldsm4(bf[q],  base + boff[q] + kB);
            #pragma unroll
            for (int mt=0;mt<4;++mt)
                #pragma unroll
                for (int nt=0;nt<4;++nt)
                    mma_f16(acc[mt][nt], af[mt], &bf[nt>>1][(nt&1)*2]);
        }
        __syncthreads();
        if (c+2 < 36) stage_issue(c+2, c&1);
    }

    #pragma unroll
    for (int mt=0;mt<4;++mt){
        int oc = wm*64 + mt*16 + g;
        float b0 = sBias[oc], b1 = sBias[oc+8];
        #pragma unroll
        for (int nt=0;nt<4;++nt){
            int n = wn*32 + nt*8 + 2*tg;
            float* o0 = out + ((size_t)b*COUT + oc)*HW + px0 + n;
            float* o1 = out + ((size_t)b*COUT + oc + 8)*HW + px0 + n;
            *(float2*)o0 = make_float2(acc[mt][nt][0]+b0, acc[mt][nt][1]+b0);
            *(float2*)o1 = make_float2(acc[mt][nt][2]+b1, acc[mt][nt][3]+b1);
        }
    }
}

// ---------------- launch ----------------
extern "C" void kernel_launch(void* const* d_in, const int* in_sizes, int n_in,
                              void* d_out, int out_size){
    const float* x0     = (const float*)d_in[0];
    const float* x1     = (const float*)d_in[1];
    const float* fc_w   = (const float*)d_in[2];
    const float* ln_g   = (const float*)d_in[3];
    const float* ln_b   = (const float*)d_in[4];
    const float* ch_w   = (const float*)d_in[5];
    const float* ch_b   = (const float*)d_in[6];
    const float* fl_w   = (const float*)d_in[7];
    const float* fl_b   = (const float*)d_in[8];
    const float* sp_w   = (const float*)d_in[9];
    const float* sp_b   = (const float*)d_in[10];
    const float* kn_w   = (const float*)d_in[11];
    const float* kn_b   = (const float*)d_in[12];
    const float* weight = (const float*)d_in[13];
    const float* mlp_w1 = (const float*)d_in[14];
    const float* mlp_b1 = (const float*)d_in[15];
    const float* mlp_w2 = (const float*)d_in[16];
    const float* mlp_b2 = (const float*)d_in[17];
    const float* fuse_w = (const float*)d_in[18];
    const float* fuse_b = (const float*)d_in[19];
    float* out = (float*)d_out;

    cudaFuncSetAttribute(k_conv, cudaFuncAttributeMaxDynamicSharedMemorySize, SMEM_BYTES);

    k_trs<<<dim3(HW/128, CIN/32, BB), 256>>>(x0, x1);
    k_red<<<BB*CIN, 64>>>();
    k_att<<<BB, 128>>>(fc_w, ln_g, ln_b, ch_w, ch_b, fl_w, fl_b,
                       sp_w, sp_b, kn_w, kn_b, mlp_w1, mlp_b1, mlp_w2, mlp_b2);
    k_agg<<<dim3(576, PB), 256>>>(weight);
    k_ftr<<<2*COUT, COUT>>>(fuse_w);
    k_wf <<<dim3(36, PB), 256>>>();
    k_conv<<<dim3(HW/NPX, BB), NTHR, SMEM_BYTES>>>(fuse_b, out);
}

// round 15
// speedup vs baseline: 1.0166x; 1.0166x over previous
#include <cuda_runtime.h>
#include <cuda_fp16.h>
#include <math.h>

#define BB 8
#define CIN 128
#define COUT 128
#define KN 4
#define HH 160
#define WW 160
#define ATT 16
#define MID 32
#define HW (HH*WW)
#define IKK (CIN*9)
#define PB 16

#define NPX 128
#define NTHR 256
#define STG_BYTES 32768        // per stage: A 16KB + B 16KB (fp16, K-chunk 64)
#define SMEM_BYTES (3*STG_BYTES)

__device__ float g_gap0[BB*CIN];
__device__ float g_gap1[BB*CIN];
__device__ float g_fdmean[BB*CIN];
__device__ float g_fdmax[BB*CIN];
__device__ float g_ca[PB*CIN];
__device__ float g_fa[PB*COUT];
__device__ float g_sM[PB*9];
__device__ float g_ka[PB*KN];
__device__ float g_A[PB*COUT*IKK];
__device__ float g_fuseT[2*COUT*COUT];
__device__ __align__(16) __half g_WfT[(size_t)PB*9*COUT*CIN];  // [pb][tap][oc][ic]
__device__ __align__(16) __half g_xT[(size_t)PB*HW*CIN];       // fp16 NHWC

__device__ __forceinline__ float sigm(float x){ return 1.f/(1.f+expf(-x)); }
__device__ __forceinline__ unsigned smem_u32(const void* p){
    unsigned a;
    asm("{ .reg .u64 t; cvta.to.shared.u64 t, %1; cvt.u32.u64 %0, t; }" : "=r"(a) : "l"(p));
    return a;
}
__device__ __forceinline__ void mma_f16(float* c, const unsigned* a, const unsigned* b){
    asm volatile(
        "mma.sync.aligned.m16n8k16.row.col.f32.f16.f16.f32 "
        "{%0,%1,%2,%3}, {%4,%5,%6,%7}, {%8,%9}, {%0,%1,%2,%3};"
        : "+f"(c[0]), "+f"(c[1]), "+f"(c[2]), "+f"(c[3])
        : "r"(a[0]), "r"(a[1]), "r"(a[2]), "r"(a[3]), "r"(b[0]), "r"(b[1]));
}
__device__ __forceinline__ void ldsm4(unsigned* d, unsigned addr){
    asm volatile("ldmatrix.sync.aligned.m8n8.x4.shared.b16 {%0,%1,%2,%3}, [%4];"
        : "=r"(d[0]),"=r"(d[1]),"=r"(d[2]),"=r"(d[3]) : "r"(addr));
}
__device__ __forceinline__ void cp16(unsigned dst, const void* src, unsigned sz){
    asm volatile("cp.async.ca.shared.global [%0], [%1], 16, %2;"
        :: "r"(dst), "l"(src), "r"(sz) : "memory");
}

// ---------------- k_stats ----------------
__global__ __launch_bounds__(256) void k_stats(const float* __restrict__ x0,
                                               const float* __restrict__ x1){
    int bc = blockIdx.x;
    const float4* p0 = (const float4*)(x0 + (size_t)bc*HW);
    const float4* p1 = (const float4*)(x1 + (size_t)bc*HW);
    float s0=0.f, s1=0.f, mx=-3.0e38f;
    for (int i = threadIdx.x; i < HW/4; i += 256){
        float4 a = p0[i], b = p1[i];
        s0 += (a.x+a.y)+(a.z+a.w);
        s1 += (b.x+b.y)+(b.z+b.w);
        mx = fmaxf(mx, fmaxf(fmaxf(a.x-b.x,a.y-b.y), fmaxf(a.z-b.z,a.w-b.w)));
    }
    #pragma unroll
    for (int off=16; off; off>>=1){
        s0 += __shfl_down_sync(0xffffffffu, s0, off);
        s1 += __shfl_down_sync(0xffffffffu, s1, off);
        mx  = fmaxf(mx, __shfl_down_sync(0xffffffffu, mx, off));
    }
    __shared__ float r0[8], r1[8], rm[8];
    int w = threadIdx.x >> 5;
    if ((threadIdx.x & 31) == 0){ r0[w]=s0; r1[w]=s1; rm[w]=mx; }
    __syncthreads();
    if (threadIdx.x == 0){
        float S0=0.f, S1=0.f, M=-3.0e38f;
        #pragma unroll
        for (int i=0;i<8;++i){ S0+=r0[i]; S1+=r1[i]; M=fmaxf(M, rm[i]); }
        const float inv = 1.f/(float)HW;
        g_gap0[bc]=S0*inv; g_gap1[bc]=S1*inv; g_fdmean[bc]=(S0-S1)*inv; g_fdmax[bc]=M;
    }
}

// ---------------- k_att ----------------
__global__ __launch_bounds__(128) void k_att(
    const float* __restrict__ fc_w,  const float* __restrict__ ln_g,  const float* __restrict__ ln_b,
    const float* __restrict__ ch_w,  const float* __restrict__ ch_b,
    const float* __restrict__ fl_w,  const float* __restrict__ fl_b,
    const float* __restrict__ sp_w,  const float* __restrict__ sp_b,
    const float* __restrict__ kn_w,  const float* __restrict__ kn_b,
    const float* __restrict__ mlp_w1,const float* __restrict__ mlp_b1,
    const float* __restrict__ mlp_w2,const float* __restrict__ mlp_b2)
{
    int b = blockIdx.x, tid = threadIdx.x;
    __shared__ float gA[128], gB[128], yv[ATT], hs[MID], mfd[9], kl[KN];
    gA[tid] = g_fdmean[b*CIN + tid];
    gB[tid] = g_fdmax [b*CIN + tid];
    __syncthreads();
    if (tid < MID){
        float sa_ = mlp_b1[tid], sm_ = mlp_b1[tid];
        for (int c=0;c<CIN;++c){ float w = mlp_w1[tid*CIN+c]; sa_ += w*gA[c]; sm_ += w*gB[c]; }
        hs[tid] = fmaxf(sa_,0.f) + fmaxf(sm_,0.f);
    }
    __syncthreads();
    if (tid < 9){
        float z = 2.f*mlp_b2[tid];
        for (int t=0;t<MID;++t) z += mlp_w2[tid*MID+t]*hs[t];
        mfd[tid] = sigm(z);
    }
    for (int p=0;p<2;++p){
        __syncthreads();
        gA[tid] = (p ? g_gap1 : g_gap0)[b*CIN + tid];
        __syncthreads();
        if (tid < ATT){
            float v = 0.f;
            for (int c=0;c<CIN;++c) v += fc_w[tid*CIN+c]*gA[c];
            yv[tid] = v;
        }
        __syncthreads();
        if (tid == 0){
            float mu = 0.f;
            for (int j=0;j<ATT;++j) mu += yv[j];
            mu *= (1.f/ATT);
            float var = 0.f;
            for (int j=0;j<ATT;++j){ float d = yv[j]-mu; var += d*d; }
            var *= (1.f/ATT);
            float inv = rsqrtf(var + 1e-5f);
            for (int j=0;j<ATT;++j)
                yv[j] = fmaxf(0.f, (yv[j]-mu)*inv*ln_g[j] + ln_b[j]);
        }
        __syncthreads();
        {
            float ac = ch_b[tid], af = fl_b[tid];
            for (int j=0;j<ATT;++j){ ac += ch_w[tid*ATT+j]*yv[j]; af += fl_w[tid*ATT+j]*yv[j]; }
            g_ca[(p*BB+b)*CIN  + tid] = sigm(ac);
            g_fa[(p*BB+b)*COUT + tid] = sigm(af);
        }
        if (tid < 9){
            float s = sp_b[tid];
            for (int j=0;j<ATT;++j) s += sp_w[tid*ATT+j]*yv[j];
            g_sM[(p*BB+b)*9 + tid] = sigm(s)*mfd[tid];
        }
        if (tid < KN){
            float l = kn_b[tid];
            for (int j=0;j<ATT;++j) l += kn_w[tid*ATT+j]*yv[j];
            kl[tid] = l;
        }
        __syncthreads();
        if (tid == 0){
            float m = fmaxf(fmaxf(kl[0],kl[1]), fmaxf(kl[2],kl[3]));
            float e0=expf(kl[0]-m), e1=expf(kl[1]-m), e2=expf(kl[2]-m), e3=expf(kl[3]-m);
            float s = e0+e1+e2+e3;
            g_ka[(p*BB+b)*KN+0]=e0/s; g_ka[(p*BB+b)*KN+1]=e1/s;
            g_ka[(p*BB+b)*KN+2]=e2/s; g_ka[(p*BB+b)*KN+3]=e3/s;
        }
    }
}

// ---------------- k_agg ----------------
__global__ __launch_bounds__(256) void k_agg(const float* __restrict__ weight){
    int pb  = blockIdx.y;
    int idx = blockIdx.x*256 + threadIdx.x;
    int c   = idx / IKK;
    float k0=g_ka[pb*KN+0], k1=g_ka[pb*KN+1], k2=g_ka[pb*KN+2], k3=g_ka[pb*KN+3];
    const float* w = weight + idx;
    float acc = k0*w[0] + k1*w[COUT*IKK] + k2*w[2*COUT*IKK] + k3*w[3*COUT*IKK];
    g_A[pb*(COUT*IKK) + idx] = acc * g_fa[pb*COUT + c];
}

// ---------------- k_ftr ----------------
__global__ __launch_bounds__(128) void k_ftr(const float* __restrict__ fuse_w){
    int c = blockIdx.x, o = threadIdx.x;
    g_fuseT[c*COUT + o] = fuse_w[o*(2*COUT) + c];
}

// ---------------- k_wf : fuse-GEMM + scales -> fp16 [tap][oc][ic] ----------
__global__ __launch_bounds__(256) void k_wf(){
    int pb = blockIdx.y, p = pb >> 3;
    int nt = blockIdx.x;
    int tid = threadIdx.x;
    int to = tid & 15, tn = tid >> 4;
    __shared__ __align__(16) float Fs[16][128];
    __shared__ __align__(16) float As[16][64];
    float acc[8][4];
    #pragma unroll
    for (int o=0;o<8;++o)
        #pragma unroll
        for (int n=0;n<4;++n) acc[o][n]=0.f;
    const float* Abase = g_A + (size_t)pb*(COUT*IKK);
    for (int ck=0; ck<8; ++ck){
        __syncthreads();
        #pragma unroll
        for (int j=0;j<8;++j){
            int l = j*256 + tid; int o = l & 127, cc = l >> 7;
            Fs[cc][o] = g_fuseT[(p*COUT + ck*16 + cc)*COUT + o];
        }
        #pragma unroll
        for (int j=0;j<4;++j){
            int l = j*256 + tid; int nn = l & 63, cc = l >> 6;
            As[cc][nn] = Abase[(ck*16+cc)*IKK + nt*64 + nn];
        }
        __syncthreads();
        #pragma unroll
        for (int cc=0; cc<16; ++cc){
            float4 av = *(const float4*)&As[cc][tn*4];
            float a_[4] = {av.x, av.y, av.z, av.w};
            float4 f0 = *(const float4*)&Fs[cc][to*8];
            float4 f1 = *(const float4*)&Fs[cc][to*8+4];
            float f_[8] = {f0.x,f0.y,f0.z,f0.w, f1.x,f1.y,f1.z,f1.w};
            #pragma unroll
            for (int o=0;o<8;++o)
                #pragma unroll
                for (int n=0;n<4;++n)
                    acc[o][n] = fmaf(f_[o], a_[n], acc[o][n]);
        }
    }
    __half* Wbase = g_WfT + (size_t)pb*9*COUT*CIN;
    const float* cap = g_ca + pb*CIN;
    const float* sMp = g_sM + pb*9;
    #pragma unroll
    for (int n=0;n<4;++n){
        int ikk = nt*64 + tn*4 + n;
        int ic = ikk/9, tap = ikk - ic*9;
        float sc = cap[ic]*sMp[tap];
        #pragma unroll
        for (int o=0;o<8;++o){
            int oc = to*8 + o;
            Wbase[((size_t)tap*COUT + oc)*CIN + ic] = __float2half_rn(acc[o][n]*sc);
        }
    }
}

// ---------------- k_tr : NCHW fp32 -> NHWC fp16 ----------------
__global__ __launch_bounds__(256) void k_tr(const float* __restrict__ x0,
                                            const float* __restrict__ x1){
    int px0 = blockIdx.x*128, ic0 = blockIdx.y*32, z = blockIdx.z;
    const float* src = (z >= 8 ? x1 : x0) + ((size_t)(z&7)*CIN + ic0)*HW + px0;
    __shared__ float t[32][129];
    int tid = threadIdx.x, lane = tid & 31, w = tid >> 5;
    #pragma unroll
    for (int i=0;i<4;++i){
        int ic = w + i*8;
        float4 v = *(const float4*)(src + (size_t)ic*HW + lane*4);
        t[ic][lane*4+0]=v.x; t[ic][lane*4+1]=v.y; t[ic][lane*4+2]=v.z; t[ic][lane*4+3]=v.w;
    }
    __syncthreads();
    int px = tid >> 1, icg = (tid & 1)*16;
    __half* dst = g_xT + ((size_t)z*HW + px0 + px)*CIN + ic0 + icg;
    unsigned v[8];
    #pragma unroll
    for (int j=0;j<8;++j){
        __half2 h = __floats2half2_rn(t[icg+2*j][px], t[icg+2*j+1][px]);
        v[j] = *(unsigned*)&h;
    }
    *(uint4*)(dst)     = make_uint4(v[0],v[1],v[2],v[3]);
    *(uint4*)(dst + 8) = make_uint4(v[4],v[5],v[6],v[7]);
}

// ---------------- k_conv : fp16 mma.sync, K-chunk 64, 3-stage single-barrier
__global__ __launch_bounds__(NTHR, 2) void k_conv(const float* __restrict__ fuse_b,
                                                  float* __restrict__ out){
    extern __shared__ float dsm[];
    __shared__ float sBias[128];
    int b = blockIdx.y;
    int px0 = blockIdx.x*NPX;
    int tid = threadIdx.x;
    int lane = tid & 31, wid = tid >> 5;
    int wm = wid >> 2, wn = wid & 3;
    int g = lane >> 2, tg = lane & 3;
    int sel = lane >> 3, r8 = lane & 7;
    int rowA = r8 + ((sel & 1) << 3), kselA = sel >> 1;
    int rowB = r8 + ((sel >> 1) << 3), kselB = sel & 1;
    if (tid < 128) sBias[tid] = fuse_b[tid];
    unsigned smem_base = smem_u32(dsm);

    unsigned aoff[4], boff[2];
    #pragma unroll
    for (int mt=0;mt<4;++mt) aoff[mt] = (wm*64 + mt*16 + rowA)*128;
    #pragma unroll
    for (int q=0;q<2;++q)    boff[q] = 16384 + (wn*32 + q*16 + rowB)*128;

    unsigned dstA[4]; int srcA[4];
    #pragma unroll
    for (int j=0;j<4;++j){
        int idx = j*NTHR + tid;
        int oc = idx>>3, c8 = idx&7;
        dstA[j] = oc*128 + ((c8 ^ (oc&7))<<4);
        srcA[j] = oc*CIN + c8*8;
    }
    unsigned dstB[4]; int srcB[4]; unsigned bmask[4];
    #pragma unroll
    for (int j=0;j<4;++j){
        int idx = j*NTHR + tid;
        int px = idx>>3, c8 = idx&7;
        dstB[j] = 16384 + px*128 + ((c8 ^ (px&7))<<4);
        int pg = px0 + px;
        int y = pg/WW, x = pg - y*WW;
        srcB[j] = (y*WW + x - WW - 1)*CIN + c8*8;
        unsigned m = 0;
        #pragma unroll
        for (int tap=0;tap<9;++tap){
            int dy = tap/3, dx = tap - dy*3;
            bool ok = ((unsigned)(y+dy-1) < (unsigned)HH) && ((unsigned)(x+dx-1) < (unsigned)WW);
            m |= (ok ? 1u : 0u) << tap;
        }
        bmask[j] = m;
    }

    float acc[4][4][4];
    #pragma unroll
    for (int mt=0;mt<4;++mt)
        #pragma unroll
        for (int nt=0;nt<4;++nt)
            #pragma unroll
            for (int e=0;e<4;++e) acc[mt][nt][e]=0.f;

    auto stage_issue = [&](int c, int slot){
        int p = (c>=18) ? 1 : 0;
        int rr = c - p*18;
        int tap = rr>>1, ich = rr&1;
        int dy = tap/3, dx = tap - dy*3;
        int pb = p*BB + b;
        unsigned sbase = smem_base + slot*STG_BYTES;
        const __half* Ab = g_WfT + ((size_t)pb*9 + tap)*COUT*CIN + ich*64;
        #pragma unroll
        for (int j=0;j<4;++j)
            cp16(sbase + dstA[j], Ab + srcA[j], 16);
        const __half* Bb = g_xT + (size_t)pb*HW*CIN + (dy*WW + dx)*CIN + ich*64;
        unsigned tb = 1u << tap;
        #pragma unroll
        for (int j=0;j<4;++j)
            cp16(sbase + dstB[j], Bb + srcB[j], (bmask[j] & tb) ? 16u : 0u);
        asm volatile("cp.async.commit_group;" ::: "memory");
    };

    stage_issue(0, 0);
    stage_issue(1, 1);
    int scur = 0, snext = 2;
    for (int c=0;c<36;++c){
        if (c < 34) asm volatile("cp.async.wait_group 1;" ::: "memory");
        else        asm volatile("cp.async.wait_group 0;" ::: "memory");
        __syncthreads();
        if (c+2 < 36) stage_issue(c+2, snext);   // slot disjoint from scur & in-flight
        unsigned base = smem_base + scur*STG_BYTES;
        #pragma unroll
        for (int ks=0;ks<4;++ks){
            unsigned kA = (unsigned)(((ks*2 + kselA) ^ r8) << 4);
            unsigned kB = (unsigned)(((ks*2 + kselB) ^ r8) << 4);
            unsigned af[4][4], bf[2][4];
            #pragma unroll
            for (int mt=0;mt<4;++mt) ldsm4(af[mt], base + aoff[mt] + kA);
            #pragma unroll
            for (int q=0;q<2;++q)    ldsm4(bf[q],  base + boff[q] + kB);
            #pragma unroll
            for (int mt=0;mt<4;++mt)
                #pragma unroll
                for (int nt=0;nt<4;++nt)
                    mma_f16(acc[mt][nt], af[mt], &bf[nt>>1][(nt&1)*2]);
        }
        scur = (scur==2) ? 0 : scur+1;
        snext = (snext==2) ? 0 : snext+1;
    }

    #pragma unroll
    for (int mt=0;mt<4;++mt){
        int oc = wm*64 + mt*16 + g;
        float b0 = sBias[oc], b1 = sBias[oc+8];
        #pragma unroll
        for (int nt=0;nt<4;++nt){
            int n = wn*32 + nt*8 + 2*tg;
            float* o0 = out + ((size_t)b*COUT + oc)*HW + px0 + n;
            float* o1 = out + ((size_t)b*COUT + oc + 8)*HW + px0 + n;
            *(float2*)o0 = make_float2(acc[mt][nt][0]+b0, acc[mt][nt][1]+b0);
            *(float2*)o1 = make_float2(acc[mt][nt][2]+b1, acc[mt][nt][3]+b1);
        }
    }
}

// ---------------- launch ----------------
extern "C" void kernel_launch(void* const* d_in, const int* in_sizes, int n_in,
                              void* d_out, int out_size){
    const float* x0     = (const float*)d_in[0];
    const float* x1     = (const float*)d_in[1];
    const float* fc_w   = (const float*)d_in[2];
    const float* ln_g   = (const float*)d_in[3];
    const float* ln_b   = (const float*)d_in[4];
    const float* ch_w   = (const float*)d_in[5];
    const float* ch_b   = (const float*)d_in[6];
    const float* fl_w   = (const float*)d_in[7];
    const float* fl_b   = (const float*)d_in[8];
    const float* sp_w   = (const float*)d_in[9];
    const float* sp_b   = (const float*)d_in[10];
    const float* kn_w   = (const float*)d_in[11];
    const float* kn_b   = (const float*)d_in[12];
    const float* weight = (const float*)d_in[13];
    const float* mlp_w1 = (const float*)d_in[14];
    const float* mlp_b1 = (const float*)d_in[15];
    const float* mlp_w2 = (const float*)d_in[16];
    const float* mlp_b2 = (const float*)d_in[17];
    const float* fuse_w = (const float*)d_in[18];
    const float* fuse_b = (const float*)d_in[19];
    float* out = (float*)d_out;

    cudaFuncSetAttribute(k_conv, cudaFuncAttributeMaxDynamicSharedMemorySize, SMEM_BYTES);

    k_stats<<<BB*CIN, 256>>>(x0, x1);
    k_att<<<BB, 128>>>(fc_w, ln_g, ln_b, ch_w, ch_b, fl_w, fl_b,
                       sp_w, sp_b, kn_w, kn_b, mlp_w1, mlp_b1, mlp_w2, mlp_b2);
    k_agg<<<dim3(576, PB), 256>>>(weight);
    k_ftr<<<2*COUT, COUT>>>(fuse_w);
    k_wf <<<dim3(18, PB), 256>>>();
    k_tr <<<dim3(HW/128, CIN/32, PB), 256>>>(x0, x1);
    k_conv<<<dim3(HW/NPX, BB), NTHR, SMEM_BYTES>>>(fuse_b, out);
}

// round 16
// speedup vs baseline: 1.0389x; 1.0220x over previous
#include <cuda_runtime.h>
#include <cuda_fp16.h>
#include <math.h>

#define BB 8
#define CIN 128
#define COUT 128
#define KN 4
#define HH 160
#define WW 160
#define ATT 16
#define MID 32
#define HW (HH*WW)
#define IKK (CIN*9)
#define PB 16

#define NPX 128
#define NTHR 256
#define STG_BYTES 32768        // per stage: A 16KB + B 16KB (fp16, K-chunk 64)
#define SMEM_BYTES (2*STG_BYTES)

#define NSTATS (BB*CIN)        // 1024 stats blocks
#define NFTR   256             // 256 ftr blocks
#define NTR    12800           // 200*4*16 transpose blocks
#define NPRE   (NSTATS+NFTR+NTR)   // 14080 (divisible by 11: 14080 = 11*1280)

__device__ float g_gap0[BB*CIN];
__device__ float g_gap1[BB*CIN];
__device__ float g_fdmean[BB*CIN];
__device__ float g_fdmax[BB*CIN];
__device__ float g_ca[PB*CIN];
__device__ float g_fa[PB*COUT];
__device__ float g_sM[PB*9];
__device__ float g_ka[PB*KN];
__device__ float g_A[PB*COUT*IKK];
__device__ float g_fuseT[2*COUT*COUT];
__device__ __align__(16) __half g_WfT[(size_t)PB*9*COUT*CIN];  // [pb][tap][oc][ic]
__device__ __align__(16) __half g_xT[(size_t)PB*HW*CIN];       // fp16 NHWC

__device__ __forceinline__ float sigm(float x){ return 1.f/(1.f+expf(-x)); }
__device__ __forceinline__ unsigned smem_u32(const void* p){
    unsigned a;
    asm("{ .reg .u64 t; cvta.to.shared.u64 t, %1; cvt.u32.u64 %0, t; }" : "=r"(a) : "l"(p));
    return a;
}
__device__ __forceinline__ void mma_f16(float* c, const unsigned* a, const unsigned* b){
    asm volatile(
        "mma.sync.aligned.m16n8k16.row.col.f32.f16.f16.f32 "
        "{%0,%1,%2,%3}, {%4,%5,%6,%7}, {%8,%9}, {%0,%1,%2,%3};"
        : "+f"(c[0]), "+f"(c[1]), "+f"(c[2]), "+f"(c[3])
        : "r"(a[0]), "r"(a[1]), "r"(a[2]), "r"(a[3]), "r"(b[0]), "r"(b[1]));
}
__device__ __forceinline__ void ldsm4(unsigned* d, unsigned addr){
    asm volatile("ldmatrix.sync.aligned.m8n8.x4.shared.b16 {%0,%1,%2,%3}, [%4];"
        : "=r"(d[0]),"=r"(d[1]),"=r"(d[2]),"=r"(d[3]) : "r"(addr));
}
__device__ __forceinline__ void cp16(unsigned dst, const void* src, unsigned sz){
    asm volatile("cp.async.ca.shared.global [%0], [%1], 16, %2;"
        :: "r"(dst), "l"(src), "r"(sz) : "memory");
}

// ---------------- k_pre : fused stats + fuse-transpose + NHWC fp16 transpose
// Role interleave: every 11th block is special (1280 = 1024 stats + 256 ftr),
// the rest (12800) are transpose blocks. Mixes latency-bound and BW-bound
// roles within each scheduling wave.
__global__ __launch_bounds__(256) void k_pre(const float* __restrict__ x0,
                                             const float* __restrict__ x1,
                                             const float* __restrict__ fuse_w){
    __shared__ float t[32][129];
    __shared__ float r0[8], r1[8], rm[8];
    int id = blockIdx.x, tid = threadIdx.x;

    if (id % 11 == 0){
        int s = id / 11;                         // 0..1279
        if (s < NSTATS){
            // ---- stats role (same arithmetic as original k_stats) ----
            int bc = s;
            const float4* p0 = (const float4*)(x0 + (size_t)bc*HW);
            const float4* p1 = (const float4*)(x1 + (size_t)bc*HW);
            float s0=0.f, s1=0.f, mx=-3.0e38f;
            for (int i = tid; i < HW/4; i += 256){
                float4 a = p0[i], b = p1[i];
                s0 += (a.x+a.y)+(a.z+a.w);
                s1 += (b.x+b.y)+(b.z+b.w);
                mx = fmaxf(mx, fmaxf(fmaxf(a.x-b.x,a.y-b.y), fmaxf(a.z-b.z,a.w-b.w)));
            }
            #pragma unroll
            for (int off=16; off; off>>=1){
                s0 += __shfl_down_sync(0xffffffffu, s0, off);
                s1 += __shfl_down_sync(0xffffffffu, s1, off);
                mx  = fmaxf(mx, __shfl_down_sync(0xffffffffu, mx, off));
            }
            int w = tid >> 5;
            if ((tid & 31) == 0){ r0[w]=s0; r1[w]=s1; rm[w]=mx; }
            __syncthreads();
            if (tid == 0){
                float S0=0.f, S1=0.f, M=-3.0e38f;
                #pragma unroll
                for (int i=0;i<8;++i){ S0+=r0[i]; S1+=r1[i]; M=fmaxf(M, rm[i]); }
                const float inv = 1.f/(float)HW;
                g_gap0[bc]=S0*inv; g_gap1[bc]=S1*inv; g_fdmean[bc]=(S0-S1)*inv; g_fdmax[bc]=M;
            }
        } else {
            // ---- fuse transpose role ----
            int idx = (s - NSTATS)*256 + tid;    // < 65536
            int o = idx & 127, c = idx >> 7;
            g_fuseT[c*COUT + o] = fuse_w[o*(2*COUT) + c];
        }
        return;
    }

    // ---- transpose role ----
    int tr = id - (id/11 + 1);                   // 0..12799
    int tx = tr % 200;
    int rest = tr / 200;
    int icg4 = rest & 3, z = rest >> 2;
    int px0 = tx*128, ic0 = icg4*32;
    const float* src = (z >= 8 ? x1 : x0) + ((size_t)(z&7)*CIN + ic0)*HW + px0;
    int lane = tid & 31, w = tid >> 5;
    #pragma unroll
    for (int i=0;i<4;++i){
        int ic = w + i*8;
        float4 v = *(const float4*)(src + (size_t)ic*HW + lane*4);
        t[ic][lane*4+0]=v.x; t[ic][lane*4+1]=v.y; t[ic][lane*4+2]=v.z; t[ic][lane*4+3]=v.w;
    }
    __syncthreads();
    int px = tid >> 1, icg = (tid & 1)*16;
    __half* dst = g_xT + ((size_t)z*HW + px0 + px)*CIN + ic0 + icg;
    unsigned v[8];
    #pragma unroll
    for (int j=0;j<8;++j){
        __half2 h = __floats2half2_rn(t[icg+2*j][px], t[icg+2*j+1][px]);
        v[j] = *(unsigned*)&h;
    }
    *(uint4*)(dst)     = make_uint4(v[0],v[1],v[2],v[3]);
    *(uint4*)(dst + 8) = make_uint4(v[4],v[5],v[6],v[7]);
}

// ---------------- k_att ----------------
__global__ __launch_bounds__(128) void k_att(
    const float* __restrict__ fc_w,  const float* __restrict__ ln_g,  const float* __restrict__ ln_b,
    const float* __restrict__ ch_w,  const float* __restrict__ ch_b,
    const float* __restrict__ fl_w,  const float* __restrict__ fl_b,
    const float* __restrict__ sp_w,  const float* __restrict__ sp_b,
    const float* __restrict__ kn_w,  const float* __restrict__ kn_b,
    const float* __restrict__ mlp_w1,const float* __restrict__ mlp_b1,
    const float* __restrict__ mlp_w2,const float* __restrict__ mlp_b2)
{
    int b = blockIdx.x, tid = threadIdx.x;
    __shared__ float gA[128], gB[128], yv[ATT], hs[MID], mfd[9], kl[KN];
    gA[tid] = g_fdmean[b*CIN + tid];
    gB[tid] = g_fdmax [b*CIN + tid];
    __syncthreads();
    if (tid < MID){
        float sa_ = mlp_b1[tid], sm_ = mlp_b1[tid];
        for (int c=0;c<CIN;++c){ float w = mlp_w1[tid*CIN+c]; sa_ += w*gA[c]; sm_ += w*gB[c]; }
        hs[tid] = fmaxf(sa_,0.f) + fmaxf(sm_,0.f);
    }
    __syncthreads();
    if (tid < 9){
        float z = 2.f*mlp_b2[tid];
        for (int t=0;t<MID;++t) z += mlp_w2[tid*MID+t]*hs[t];
        mfd[tid] = sigm(z);
    }
    for (int p=0;p<2;++p){
        __syncthreads();
        gA[tid] = (p ? g_gap1 : g_gap0)[b*CIN + tid];
        __syncthreads();
        if (tid < ATT){
            float v = 0.f;
            for (int c=0;c<CIN;++c) v += fc_w[tid*CIN+c]*gA[c];
            yv[tid] = v;
        }
        __syncthreads();
        if (tid == 0){
            float mu = 0.f;
            for (int j=0;j<ATT;++j) mu += yv[j];
            mu *= (1.f/ATT);
            float var = 0.f;
            for (int j=0;j<ATT;++j){ float d = yv[j]-mu; var += d*d; }
            var *= (1.f/ATT);
            float inv = rsqrtf(var + 1e-5f);
            for (int j=0;j<ATT;++j)
                yv[j] = fmaxf(0.f, (yv[j]-mu)*inv*ln_g[j] + ln_b[j]);
        }
        __syncthreads();
        {
            float ac = ch_b[tid], af = fl_b[tid];
            for (int j=0;j<ATT;++j){ ac += ch_w[tid*ATT+j]*yv[j]; af += fl_w[tid*ATT+j]*yv[j]; }
            g_ca[(p*BB+b)*CIN  + tid] = sigm(ac);
            g_fa[(p*BB+b)*COUT + tid] = sigm(af);
        }
        if (tid < 9){
            float s = sp_b[tid];
            for (int j=0;j<ATT;++j) s += sp_w[tid*ATT+j]*yv[j];
            g_sM[(p*BB+b)*9 + tid] = sigm(s)*mfd[tid];
        }
        if (tid < KN){
            float l = kn_b[tid];
            for (int j=0;j<ATT;++j) l += kn_w[tid*ATT+j]*yv[j];
            kl[tid] = l;
        }
        __syncthreads();
        if (tid == 0){
            float m = fmaxf(fmaxf(kl[0],kl[1]), fmaxf(kl[2],kl[3]));
            float e0=expf(kl[0]-m), e1=expf(kl[1]-m), e2=expf(kl[2]-m), e3=expf(kl[3]-m);
            float s = e0+e1+e2+e3;
            g_ka[(p*BB+b)*KN+0]=e0/s; g_ka[(p*BB+b)*KN+1]=e1/s;
            g_ka[(p*BB+b)*KN+2]=e2/s; g_ka[(p*BB+b)*KN+3]=e3/s;
        }
    }
}

// ---------------- k_agg ----------------
__global__ __launch_bounds__(256) void k_agg(const float* __restrict__ weight){
    int pb  = blockIdx.y;
    int idx = blockIdx.x*256 + threadIdx.x;
    int c   = idx / IKK;
    float k0=g_ka[pb*KN+0], k1=g_ka[pb*KN+1], k2=g_ka[pb*KN+2], k3=g_ka[pb*KN+3];
    const float* w = weight + idx;
    float acc = k0*w[0] + k1*w[COUT*IKK] + k2*w[2*COUT*IKK] + k3*w[3*COUT*IKK];
    g_A[pb*(COUT*IKK) + idx] = acc * g_fa[pb*COUT + c];
}

// ---------------- k_wf : fuse-GEMM + scales -> fp16 [tap][oc][ic] ----------
// grid (36 ntiles of 32 ikk, 16 pb) = 576 blocks for >1 wave occupancy.
__global__ __launch_bounds__(256) void k_wf(){
    int pb = blockIdx.y, p = pb >> 3;
    int nt = blockIdx.x;
    int tid = threadIdx.x;
    int to = tid & 15, tn = tid >> 4;
    __shared__ __align__(16) float Fs[16][128];
    __shared__ __align__(16) float As[16][32];
    float acc[8][2];
    #pragma unroll
    for (int o=0;o<8;++o){ acc[o][0]=0.f; acc[o][1]=0.f; }
    const float* Abase = g_A + (size_t)pb*(COUT*IKK);
    for (int ck=0; ck<8; ++ck){
        __syncthreads();
        #pragma unroll
        for (int j=0;j<8;++j){
            int l = j*256 + tid; int o = l & 127, cc = l >> 7;
            Fs[cc][o] = g_fuseT[(p*COUT + ck*16 + cc)*COUT + o];
        }
        {
            int l = tid*2; int nn = l & 31, cc = l >> 5;
            *(float2*)&As[cc][nn] = *(const float2*)&Abase[(ck*16+cc)*IKK + nt*32 + nn];
        }
        __syncthreads();
        #pragma unroll
        for (int cc=0; cc<16; ++cc){
            float2 av = *(const float2*)&As[cc][tn*2];
            float4 f0 = *(const float4*)&Fs[cc][to*8];
            float4 f1 = *(const float4*)&Fs[cc][to*8+4];
            float f_[8] = {f0.x,f0.y,f0.z,f0.w, f1.x,f1.y,f1.z,f1.w};
            #pragma unroll
            for (int o=0;o<8;++o){
                acc[o][0] = fmaf(f_[o], av.x, acc[o][0]);
                acc[o][1] = fmaf(f_[o], av.y, acc[o][1]);
            }
        }
    }
    __half* Wbase = g_WfT + (size_t)pb*9*COUT*CIN;
    const float* cap = g_ca + pb*CIN;
    const float* sMp = g_sM + pb*9;
    #pragma unroll
    for (int n=0;n<2;++n){
        int ikk = nt*32 + tn*2 + n;
        int ic = ikk/9, tap = ikk - ic*9;
        float sc = cap[ic]*sMp[tap];
        #pragma unroll
        for (int o=0;o<8;++o){
            int oc = to*8 + o;
            Wbase[((size_t)tap*COUT + oc)*CIN + ic] = __float2half_rn(acc[o][n]*sc);
        }
    }
}

// ---------------- k_conv : fp16 mma.sync m16n8k16, K-chunk 64, 2-stage ------
__global__ __launch_bounds__(NTHR, 2) void k_conv(const float* __restrict__ fuse_b,
                                                  float* __restrict__ out){
    extern __shared__ float dsm[];
    __shared__ float sBias[128];
    int b = blockIdx.y;
    int px0 = blockIdx.x*NPX;
    int tid = threadIdx.x;
    int lane = tid & 31, wid = tid >> 5;
    int wm = wid >> 2, wn = wid & 3;
    int g = lane >> 2, tg = lane & 3;
    int sel = lane >> 3, r8 = lane & 7;
    int rowA = r8 + ((sel & 1) << 3), kselA = sel >> 1;
    int rowB = r8 + ((sel >> 1) << 3), kselB = sel & 1;
    if (tid < 128) sBias[tid] = fuse_b[tid];
    unsigned smem_base = smem_u32(dsm);

    unsigned aoff[4], boff[2];
    #pragma unroll
    for (int mt=0;mt<4;++mt) aoff[mt] = (wm*64 + mt*16 + rowA)*128;
    #pragma unroll
    for (int q=0;q<2;++q)    boff[q] = 16384 + (wn*32 + q*16 + rowB)*128;

    unsigned dstA[4]; int srcA[4];
    #pragma unroll
    for (int j=0;j<4;++j){
        int idx = j*NTHR + tid;
        int oc = idx>>3, c8 = idx&7;
        dstA[j] = oc*128 + ((c8 ^ (oc&7))<<4);
        srcA[j] = oc*CIN + c8*8;
    }
    unsigned dstB[4]; int srcB[4]; unsigned bmask[4];
    #pragma unroll
    for (int j=0;j<4;++j){
        int idx = j*NTHR + tid;
        int px = idx>>3, c8 = idx&7;
        dstB[j] = 16384 + px*128 + ((c8 ^ (px&7))<<4);
        int pg = px0 + px;
        int y = pg/WW, x = pg - y*WW;
        srcB[j] = (y*WW + x - WW - 1)*CIN + c8*8;
        unsigned m = 0;
        #pragma unroll
        for (int tap=0;tap<9;++tap){
            int dy = tap/3, dx = tap - dy*3;
            bool ok = ((unsigned)(y+dy-1) < (unsigned)HH) && ((unsigned)(x+dx-1) < (unsigned)WW);
            m |= (ok ? 1u : 0u) << tap;
        }
        bmask[j] = m;
    }

    float acc[4][4][4];
    #pragma unroll
    for (int mt=0;mt<4;++mt)
        #pragma unroll
        for (int nt=0;nt<4;++nt)
            #pragma unroll
            for (int e=0;e<4;++e) acc[mt][nt][e]=0.f;

    auto stage_issue = [&](int c, int slot){
        int p = (c>=18) ? 1 : 0;
        int rr = c - p*18;
        int tap = rr>>1, ich = rr&1;
        int dy = tap/3, dx = tap - dy*3;
        int pb = p*BB + b;
        unsigned sbase = smem_base + slot*STG_BYTES;
        const __half* Ab = g_WfT + ((size_t)pb*9 + tap)*COUT*CIN + ich*64;
        #pragma unroll
        for (int j=0;j<4;++j)
            cp16(sbase + dstA[j], Ab + srcA[j], 16);
        const __half* Bb = g_xT + (size_t)pb*HW*CIN + (dy*WW + dx)*CIN + ich*64;
        unsigned tb = 1u << tap;
        #pragma unroll
        for (int j=0;j<4;++j)
            cp16(sbase + dstB[j], Bb + srcB[j], (bmask[j] & tb) ? 16u : 0u);
        asm volatile("cp.async.commit_group;" ::: "memory");
    };

    stage_issue(0, 0);
    stage_issue(1, 1);
    for (int c=0;c<36;++c){
        if (c < 34) asm volatile("cp.async.wait_group 1;" ::: "memory");
        else        asm volatile("cp.async.wait_group 0;" ::: "memory");
        __syncthreads();
        unsigned base = smem_base + (c&1)*STG_BYTES;
        #pragma unroll
        for (int ks=0;ks<4;++ks){
            unsigned kA = (unsigned)(((ks*2 + kselA) ^ r8) << 4);
            unsigned kB = (unsigned)(((ks*2 + kselB) ^ r8) << 4);
            unsigned af[4][4], bf[2][4];
            #pragma unroll
            for (int mt=0;mt<4;++mt) ldsm4(af[mt], base + aoff[mt] + kA);
            #pragma unroll
            for (int q=0;q<2;++q)    ldsm4(bf[q],  base + boff[q] + kB);
            #pragma unroll
            for (int mt=0;mt<4;++mt)
                #pragma unroll
                for (int nt=0;nt<4;++nt)
                    mma_f16(acc[mt][nt], af[mt], &bf[nt>>1][(nt&1)*2]);
        }
        __syncthreads();
        if (c+2 < 36) stage_issue(c+2, c&1);
    }

    #pragma unroll
    for (int mt=0;mt<4;++mt){
        int oc = wm*64 + mt*16 + g;
        float b0 = sBias[oc], b1 = sBias[oc+8];
        #pragma unroll
        for (int nt=0;nt<4;++nt){
            int n = wn*32 + nt*8 + 2*tg;
            float* o0 = out + ((size_t)b*COUT + oc)*HW + px0 + n;
            float* o1 = out + ((size_t)b*COUT + oc + 8)*HW + px0 + n;
            *(float2*)o0 = make_float2(acc[mt][nt][0]+b0, acc[mt][nt][1]+b0);
            *(float2*)o1 = make_float2(acc[mt][nt][2]+b1, acc[mt][nt][3]+b1);
        }
    }
}

// ---------------- launch ----------------
extern "C" void kernel_launch(void* const* d_in, const int* in_sizes, int n_in,
                              void* d_out, int out_size){
    const float* x0     = (const float*)d_in[0];
    const float* x1     = (const float*)d_in[1];
    const float* fc_w   = (const float*)d_in[2];
    const float* ln_g   = (const float*)d_in[3];
    const float* ln_b   = (const float*)d_in[4];
    const float* ch_w   = (const float*)d_in[5];
    const float* ch_b   = (const float*)d_in[6];
    const float* fl_w   = (const float*)d_in[7];
    const float* fl_b   = (const float*)d_in[8];
    const float* sp_w   = (const float*)d_in[9];
    const float* sp_b   = (const float*)d_in[10];
    const float* kn_w   = (const float*)d_in[11];
    const float* kn_b   = (const float*)d_in[12];
    const float* weight = (const float*)d_in[13];
    const float* mlp_w1 = (const float*)d_in[14];
    const float* mlp_b1 = (const float*)d_in[15];
    const float* mlp_w2 = (const float*)d_in[16];
    const float* mlp_b2 = (const float*)d_in[17];
    const float* fuse_w = (const float*)d_in[18];
    const float* fuse_b = (const float*)d_in[19];
    float* out = (float*)d_out;

    cudaFuncSetAttribute(k_conv, cudaFuncAttributeMaxDynamicSharedMemorySize, SMEM_BYTES);

    k_pre<<<NPRE, 256>>>(x0, x1, fuse_w);
    k_att<<<BB, 128>>>(fc_w, ln_g, ln_b, ch_w, ch_b, fl_w, fl_b,
                       sp_w, sp_b, kn_w, kn_b, mlp_w1, mlp_b1, mlp_w2, mlp_b2);
    k_agg<<<dim3(576, PB), 256>>>(weight);
    k_wf <<<dim3(36, PB), 256>>>();
    k_conv<<<dim3(HW/NPX, BB), NTHR, SMEM_BYTES>>>(fuse_b, out);
}

// round 17
// speedup vs baseline: 1.1071x; 1.0656x over previous
#include <cuda_runtime.h>
#include <cuda_fp16.h>
#include <math.h>

#define BB 8
#define CIN 128
#define COUT 128
#define KN 4
#define HH 160
#define WW 160
#define ATT 16
#define MID 32
#define HW (HH*WW)
#define IKK (CIN*9)
#define PB 16

#define NPX 128
#define NTHR 256
#define STG_BYTES 32768        // per stage: A 16KB + B 16KB (fp16, K-chunk 64)
#define SMEM_BYTES (2*STG_BYTES)

#define NSTATS (BB*CIN)        // 1024 stats blocks
#define NFTR   256             // 256 ftr blocks
#define NTR    12800           // 200*4*16 transpose blocks
#define NPRE   (NSTATS+NFTR+NTR)   // 14080 = 11*1280

__device__ float g_gap0[BB*CIN];
__device__ float g_gap1[BB*CIN];
__device__ float g_fdmean[BB*CIN];
__device__ float g_fdmax[BB*CIN];
__device__ float g_ca[PB*CIN];
__device__ float g_fa[PB*COUT];
__device__ float g_sM[PB*9];
__device__ float g_ka[PB*KN];
__device__ float g_A[PB*COUT*IKK];
__device__ float g_fuseT[2*COUT*COUT];
__device__ __align__(16) __half g_WfT[(size_t)PB*9*COUT*CIN];  // [pb][tap][oc][ic]
__device__ __align__(16) __half g_xT[(size_t)PB*HW*CIN];       // fp16 NHWC

__device__ __forceinline__ float sigm(float x){ return 1.f/(1.f+expf(-x)); }
__device__ __forceinline__ unsigned smem_u32(const void* p){
    unsigned a;
    asm("{ .reg .u64 t; cvta.to.shared.u64 t, %1; cvt.u32.u64 %0, t; }" : "=r"(a) : "l"(p));
    return a;
}
__device__ __forceinline__ void mma_f16(float* c, const unsigned* a, const unsigned* b){
    asm volatile(
        "mma.sync.aligned.m16n8k16.row.col.f32.f16.f16.f32 "
        "{%0,%1,%2,%3}, {%4,%5,%6,%7}, {%8,%9}, {%0,%1,%2,%3};"
        : "+f"(c[0]), "+f"(c[1]), "+f"(c[2]), "+f"(c[3])
        : "r"(a[0]), "r"(a[1]), "r"(a[2]), "r"(a[3]), "r"(b[0]), "r"(b[1]));
}
__device__ __forceinline__ void ldsm4(unsigned* d, unsigned addr){
    asm volatile("ldmatrix.sync.aligned.m8n8.x4.shared.b16 {%0,%1,%2,%3}, [%4];"
        : "=r"(d[0]),"=r"(d[1]),"=r"(d[2]),"=r"(d[3]) : "r"(addr));
}
__device__ __forceinline__ void cp16(unsigned dst, const void* src, unsigned sz){
    asm volatile("cp.async.ca.shared.global [%0], [%1], 16, %2;"
        :: "r"(dst), "l"(src), "r"(sz) : "memory");
}

// ---------------- k_pre : fused stats + fuse-transpose + NHWC fp16 transpose
__global__ __launch_bounds__(256) void k_pre(const float* __restrict__ x0,
                                             const float* __restrict__ x1,
                                             const float* __restrict__ fuse_w){
    __shared__ float t[32][129];
    __shared__ float r0[8], r1[8], rm[8];
    int id = blockIdx.x, tid = threadIdx.x;

    if (id % 11 == 0){
        int s = id / 11;
        if (s < NSTATS){
            int bc = s;
            const float4* p0 = (const float4*)(x0 + (size_t)bc*HW);
            const float4* p1 = (const float4*)(x1 + (size_t)bc*HW);
            float s0=0.f, s1=0.f, mx=-3.0e38f;
            for (int i = tid; i < HW/4; i += 256){
                float4 a = p0[i], b = p1[i];
                s0 += (a.x+a.y)+(a.z+a.w);
                s1 += (b.x+b.y)+(b.z+b.w);
                mx = fmaxf(mx, fmaxf(fmaxf(a.x-b.x,a.y-b.y), fmaxf(a.z-b.z,a.w-b.w)));
            }
            #pragma unroll
            for (int off=16; off; off>>=1){
                s0 += __shfl_down_sync(0xffffffffu, s0, off);
                s1 += __shfl_down_sync(0xffffffffu, s1, off);
                mx  = fmaxf(mx, __shfl_down_sync(0xffffffffu, mx, off));
            }
            int w = tid >> 5;
            if ((tid & 31) == 0){ r0[w]=s0; r1[w]=s1; rm[w]=mx; }
            __syncthreads();
            if (tid == 0){
                float S0=0.f, S1=0.f, M=-3.0e38f;
                #pragma unroll
                for (int i=0;i<8;++i){ S0+=r0[i]; S1+=r1[i]; M=fmaxf(M, rm[i]); }
                const float inv = 1.f/(float)HW;
                g_gap0[bc]=S0*inv; g_gap1[bc]=S1*inv; g_fdmean[bc]=(S0-S1)*inv; g_fdmax[bc]=M;
            }
        } else {
            int idx = (s - NSTATS)*256 + tid;
            int o = idx & 127, c = idx >> 7;
            g_fuseT[c*COUT + o] = fuse_w[o*(2*COUT) + c];
        }
        return;
    }

    int tr = id - (id/11 + 1);
    int tx = tr % 200;
    int rest = tr / 200;
    int icg4 = rest & 3, z = rest >> 2;
    int px0 = tx*128, ic0 = icg4*32;
    const float* src = (z >= 8 ? x1 : x0) + ((size_t)(z&7)*CIN + ic0)*HW + px0;
    int lane = tid & 31, w = tid >> 5;
    #pragma unroll
    for (int i=0;i<4;++i){
        int ic = w + i*8;
        float4 v = *(const float4*)(src + (size_t)ic*HW + lane*4);
        t[ic][lane*4+0]=v.x; t[ic][lane*4+1]=v.y; t[ic][lane*4+2]=v.z; t[ic][lane*4+3]=v.w;
    }
    __syncthreads();
    int px = tid >> 1, icg = (tid & 1)*16;
    __half* dst = g_xT + ((size_t)z*HW + px0 + px)*CIN + ic0 + icg;
    unsigned v[8];
    #pragma unroll
    for (int j=0;j<8;++j){
        __half2 h = __floats2half2_rn(t[icg+2*j][px], t[icg+2*j+1][px]);
        v[j] = *(unsigned*)&h;
    }
    *(uint4*)(dst)     = make_uint4(v[0],v[1],v[2],v[3]);
    *(uint4*)(dst + 8) = make_uint4(v[4],v[5],v[6],v[7]);
}

// ---------------- k_att ----------------
__global__ __launch_bounds__(128) void k_att(
    const float* __restrict__ fc_w,  const float* __restrict__ ln_g,  const float* __restrict__ ln_b,
    const float* __restrict__ ch_w,  const float* __restrict__ ch_b,
    const float* __restrict__ fl_w,  const float* __restrict__ fl_b,
    const float* __restrict__ sp_w,  const float* __restrict__ sp_b,
    const float* __restrict__ kn_w,  const float* __restrict__ kn_b,
    const float* __restrict__ mlp_w1,const float* __restrict__ mlp_b1,
    const float* __restrict__ mlp_w2,const float* __restrict__ mlp_b2)
{
    int b = blockIdx.x, tid = threadIdx.x;
    __shared__ float gA[128], gB[128], yv[ATT], hs[MID], mfd[9], kl[KN];
    gA[tid] = g_fdmean[b*CIN + tid];
    gB[tid] = g_fdmax [b*CIN + tid];
    __syncthreads();
    if (tid < MID){
        float sa_ = mlp_b1[tid], sm_ = mlp_b1[tid];
        for (int c=0;c<CIN;++c){ float w = mlp_w1[tid*CIN+c]; sa_ += w*gA[c]; sm_ += w*gB[c]; }
        hs[tid] = fmaxf(sa_,0.f) + fmaxf(sm_,0.f);
    }
    __syncthreads();
    if (tid < 9){
        float z = 2.f*mlp_b2[tid];
        for (int t=0;t<MID;++t) z += mlp_w2[tid*MID+t]*hs[t];
        mfd[tid] = sigm(z);
    }
    for (int p=0;p<2;++p){
        __syncthreads();
        gA[tid] = (p ? g_gap1 : g_gap0)[b*CIN + tid];
        __syncthreads();
        if (tid < ATT){
            float v = 0.f;
            for (int c=0;c<CIN;++c) v += fc_w[tid*CIN+c]*gA[c];
            yv[tid] = v;
        }
        __syncthreads();
        if (tid == 0){
            float mu = 0.f;
            for (int j=0;j<ATT;++j) mu += yv[j];
            mu *= (1.f/ATT);
            float var = 0.f;
            for (int j=0;j<ATT;++j){ float d = yv[j]-mu; var += d*d; }
            var *= (1.f/ATT);
            float inv = rsqrtf(var + 1e-5f);
            for (int j=0;j<ATT;++j)
                yv[j] = fmaxf(0.f, (yv[j]-mu)*inv*ln_g[j] + ln_b[j]);
        }
        __syncthreads();
        {
            float ac = ch_b[tid], af = fl_b[tid];
            for (int j=0;j<ATT;++j){ ac += ch_w[tid*ATT+j]*yv[j]; af += fl_w[tid*ATT+j]*yv[j]; }
            g_ca[(p*BB+b)*CIN  + tid] = sigm(ac);
            g_fa[(p*BB+b)*COUT + tid] = sigm(af);
        }
        if (tid < 9){
            float s = sp_b[tid];
            for (int j=0;j<ATT;++j) s += sp_w[tid*ATT+j]*yv[j];
            g_sM[(p*BB+b)*9 + tid] = sigm(s)*mfd[tid];
        }
        if (tid < KN){
            float l = kn_b[tid];
            for (int j=0;j<ATT;++j) l += kn_w[tid*ATT+j]*yv[j];
            kl[tid] = l;
        }
        __syncthreads();
        if (tid == 0){
            float m = fmaxf(fmaxf(kl[0],kl[1]), fmaxf(kl[2],kl[3]));
            float e0=expf(kl[0]-m), e1=expf(kl[1]-m), e2=expf(kl[2]-m), e3=expf(kl[3]-m);
            float s = e0+e1+e2+e3;
            g_ka[(p*BB+b)*KN+0]=e0/s; g_ka[(p*BB+b)*KN+1]=e1/s;
            g_ka[(p*BB+b)*KN+2]=e2/s; g_ka[(p*BB+b)*KN+3]=e3/s;
        }
    }
}

// ---------------- k_agg ----------------
__global__ __launch_bounds__(256) void k_agg(const float* __restrict__ weight){
    int pb  = blockIdx.y;
    int idx = blockIdx.x*256 + threadIdx.x;
    int c   = idx / IKK;
    float k0=g_ka[pb*KN+0], k1=g_ka[pb*KN+1], k2=g_ka[pb*KN+2], k3=g_ka[pb*KN+3];
    const float* w = weight + idx;
    float acc = k0*w[0] + k1*w[COUT*IKK] + k2*w[2*COUT*IKK] + k3*w[3*COUT*IKK];
    g_A[pb*(COUT*IKK) + idx] = acc * g_fa[pb*COUT + c];
}

// ---------------- k_wf : fuse-GEMM + scales -> fp16 [tap][oc][ic] ----------
// Lane mapping: to = tid>>4 (Fs broadcast), tn = tid&15 (As spread) -> no LDS
// bank conflicts in the inner loop. grid (18, 16).
__global__ __launch_bounds__(256) void k_wf(){
    int pb = blockIdx.y, p = pb >> 3;
    int nt = blockIdx.x;
    int tid = threadIdx.x;
    int to = tid >> 4, tn = tid & 15;
    __shared__ __align__(16) float Fs[16][128];
    __shared__ __align__(16) float As[16][64];
    float acc[8][4];
    #pragma unroll
    for (int o=0;o<8;++o)
        #pragma unroll
        for (int n=0;n<4;++n) acc[o][n]=0.f;
    const float* Abase = g_A + (size_t)pb*(COUT*IKK);
    for (int ck=0; ck<8; ++ck){
        __syncthreads();
        #pragma unroll
        for (int j=0;j<8;++j){
            int l = j*256 + tid; int o = l & 127, cc = l >> 7;
            Fs[cc][o] = g_fuseT[(p*COUT + ck*16 + cc)*COUT + o];
        }
        #pragma unroll
        for (int j=0;j<4;++j){
            int l = j*256 + tid; int nn = l & 63, cc = l >> 6;
            As[cc][nn] = Abase[(ck*16+cc)*IKK + nt*64 + nn];
        }
        __syncthreads();
        #pragma unroll
        for (int cc=0; cc<16; ++cc){
            float4 av = *(const float4*)&As[cc][tn*4];
            float a_[4] = {av.x, av.y, av.z, av.w};
            float4 f0 = *(const float4*)&Fs[cc][to*8];
            float4 f1 = *(const float4*)&Fs[cc][to*8+4];
            float f_[8] = {f0.x,f0.y,f0.z,f0.w, f1.x,f1.y,f1.z,f1.w};
            #pragma unroll
            for (int o=0;o<8;++o)
                #pragma unroll
                for (int n=0;n<4;++n)
                    acc[o][n] = fmaf(f_[o], a_[n], acc[o][n]);
        }
    }
    __half* Wbase = g_WfT + (size_t)pb*9*COUT*CIN;
    const float* cap = g_ca + pb*CIN;
    const float* sMp = g_sM + pb*9;
    #pragma unroll
    for (int n=0;n<4;++n){
        int ikk = nt*64 + tn*4 + n;
        int ic = ikk/9, tap = ikk - ic*9;
        float sc = cap[ic]*sMp[tap];
        #pragma unroll
        for (int o=0;o<8;++o){
            int oc = to*8 + o;
            Wbase[((size_t)tap*COUT + oc)*CIN + ic] = __float2half_rn(acc[o][n]*sc);
        }
    }
}

// ---------------- k_conv : fp16 mma.sync m16n8k16, K-chunk 64, 2-stage ------
__global__ __launch_bounds__(NTHR, 2) void k_conv(const float* __restrict__ fuse_b,
                                                  float* __restrict__ out){
    extern __shared__ float dsm[];
    __shared__ float sBias[128];
    int b = blockIdx.y;
    int px0 = blockIdx.x*NPX;
    int tid = threadIdx.x;
    int lane = tid & 31, wid = tid >> 5;
    int wm = wid >> 2, wn = wid & 3;
    int g = lane >> 2, tg = lane & 3;
    int sel = lane >> 3, r8 = lane & 7;
    int rowA = r8 + ((sel & 1) << 3), kselA = sel >> 1;
    int rowB = r8 + ((sel >> 1) << 3), kselB = sel & 1;
    if (tid < 128) sBias[tid] = fuse_b[tid];
    unsigned smem_base = smem_u32(dsm);

    unsigned aoff[4], boff[2];
    #pragma unroll
    for (int mt=0;mt<4;++mt) aoff[mt] = (wm*64 + mt*16 + rowA)*128;
    #pragma unroll
    for (int q=0;q<2;++q)    boff[q] = 16384 + (wn*32 + q*16 + rowB)*128;

    unsigned dstA[4]; int srcA[4];
    #pragma unroll
    for (int j=0;j<4;++j){
        int idx = j*NTHR + tid;
        int oc = idx>>3, c8 = idx&7;
        dstA[j] = oc*128 + ((c8 ^ (oc&7))<<4);
        srcA[j] = oc*CIN + c8*8;
    }
    unsigned dstB[4]; int srcB[4]; unsigned bmask[4];
    #pragma unroll
    for (int j=0;j<4;++j){
        int idx = j*NTHR + tid;
        int px = idx>>3, c8 = idx&7;
        dstB[j] = 16384 + px*128 + ((c8 ^ (px&7))<<4);
        int pg = px0 + px;
        int y = pg/WW, x = pg - y*WW;
        srcB[j] = (y*WW + x - WW - 1)*CIN + c8*8;
        unsigned m = 0;
        #pragma unroll
        for (int tap=0;tap<9;++tap){
            int dy = tap/3, dx = tap - dy*3;
            bool ok = ((unsigned)(y+dy-1) < (unsigned)HH) && ((unsigned)(x+dx-1) < (unsigned)WW);
            m |= (ok ? 1u : 0u) << tap;
        }
        bmask[j] = m;
    }

    float acc[4][4][4];
    #pragma unroll
    for (int mt=0;mt<4;++mt)
        #pragma unroll
        for (int nt=0;nt<4;++nt)
            #pragma unroll
            for (int e=0;e<4;++e) acc[mt][nt][e]=0.f;

    auto stage_issue = [&](int c, int slot){
        int p = (c>=18) ? 1 : 0;
        int rr = c - p*18;
        int tap = rr>>1, ich = rr&1;
        int dy = tap/3, dx = tap - dy*3;
        int pb = p*BB + b;
        unsigned sbase = smem_base + slot*STG_BYTES;
        const __half* Ab = g_WfT + ((size_t)pb*9 + tap)*COUT*CIN + ich*64;
        #pragma unroll
        for (int j=0;j<4;++j)
            cp16(sbase + dstA[j], Ab + srcA[j], 16);
        const __half* Bb = g_xT + (size_t)pb*HW*CIN + (dy*WW + dx)*CIN + ich*64;
        unsigned tb = 1u << tap;
        #pragma unroll
        for (int j=0;j<4;++j)
            cp16(sbase + dstB[j], Bb + srcB[j], (bmask[j] & tb) ? 16u : 0u);
        asm volatile("cp.async.commit_group;" ::: "memory");
    };

    stage_issue(0, 0);
    stage_issue(1, 1);
    for (int c=0;c<36;++c){
        if (c < 34) asm volatile("cp.async.wait_group 1;" ::: "memory");
        else        asm volatile("cp.async.wait_group 0;" ::: "memory");
        __syncthreads();
        unsigned base = smem_base + (c&1)*STG_BYTES;
        #pragma unroll
        for (int ks=0;ks<4;++ks){
            unsigned kA = (unsigned)(((ks*2 + kselA) ^ r8) << 4);
            unsigned kB = (unsigned)(((ks*2 + kselB) ^ r8) << 4);
            unsigned af[4][4], bf[2][4];
            #pragma unroll
            for (int mt=0;mt<4;++mt) ldsm4(af[mt], base + aoff[mt] + kA);
            #pragma unroll
            for (int q=0;q<2;++q)    ldsm4(bf[q],  base + boff[q] + kB);
            #pragma unroll
            for (int mt=0;mt<4;++mt)
                #pragma unroll
                for (int nt=0;nt<4;++nt)
                    mma_f16(acc[mt][nt], af[mt], &bf[nt>>1][(nt&1)*2]);
        }
        __syncthreads();
        if (c+2 < 36) stage_issue(c+2, c&1);
    }

    #pragma unroll
    for (int mt=0;mt<4;++mt){
        int oc = wm*64 + mt*16 + g;
        float b0 = sBias[oc], b1 = sBias[oc+8];
        #pragma unroll
        for (int nt=0;nt<4;++nt){
            int n = wn*32 + nt*8 + 2*tg;
            float* o0 = out + ((size_t)b*COUT + oc)*HW + px0 + n;
            float* o1 = out + ((size_t)b*COUT + oc + 8)*HW + px0 + n;
            *(float2*)o0 = make_float2(acc[mt][nt][0]+b0, acc[mt][nt][1]+b0);
            *(float2*)o1 = make_float2(acc[mt][nt][2]+b1, acc[mt][nt][3]+b1);
        }
    }
}

// ---------------- launch ----------------
extern "C" void kernel_launch(void* const* d_in, const int* in_sizes, int n_in,
                              void* d_out, int out_size){
    const float* x0     = (const float*)d_in[0];
    const float* x1     = (const float*)d_in[1];
    const float* fc_w   = (const float*)d_in[2];
    const float* ln_g   = (const float*)d_in[3];
    const float* ln_b   = (const float*)d_in[4];
    const float* ch_w   = (const float*)d_in[5];
    const float* ch_b   = (const float*)d_in[6];
    const float* fl_w   = (const float*)d_in[7];
    const float* fl_b   = (const float*)d_in[8];
    const float* sp_w   = (const float*)d_in[9];
    const float* sp_b   = (const float*)d_in[10];
    const float* kn_w   = (const float*)d_in[11];
    const float* kn_b   = (const float*)d_in[12];
    const float* weight = (const float*)d_in[13];
    const float* mlp_w1 = (const float*)d_in[14];
    const float* mlp_b1 = (const float*)d_in[15];
    const float* mlp_w2 = (const float*)d_in[16];
    const float* mlp_b2 = (const float*)d_in[17];
    const float* fuse_w = (const float*)d_in[18];
    const float* fuse_b = (const float*)d_in[19];
    float* out = (float*)d_out;

    cudaFuncSetAttribute(k_conv, cudaFuncAttributeMaxDynamicSharedMemorySize, SMEM_BYTES);

    k_pre<<<NPRE, 256>>>(x0, x1, fuse_w);
    k_att<<<BB, 128>>>(fc_w, ln_g, ln_b, ch_w, ch_b, fl_w, fl_b,
                       sp_w, sp_b, kn_w, kn_b, mlp_w1, mlp_b1, mlp_w2, mlp_b2);
    k_agg<<<dim3(576, PB), 256>>>(weight);
    k_wf <<<dim3(18, PB), 256>>>();
    k_conv<<<dim3(HW/NPX, BB), NTHR, SMEM_BYTES>>>(fuse_b, out);
}